// round 6
// baseline (speedup 1.0000x reference)
#include <cuda_runtime.h>
#include <cuda_bf16.h>
#include <cstdint>

#define BB 256
#define NN 512
#define DD 6
#define FF 128
#define MAXDEG 6
#define BN (BB * NN)
#define TM 128
#define SSTR 136   // smem row stride in bf16 elems (128 + 8 pad)

// ---- smem byte offsets ----
#define SM_SH   0                      // Sh: 128 x SSTR bf16 (34816B)
#define SM_SL   34816
#define SM_WH   69632
#define SM_WL   104448
#define SM_NODE 139264                 // 128 ints
#define SM_BIAS 139776                 // 128 floats
#define SM_BYTES 140288

// ---- device scratch (allocation-free rule) ----
__device__ int g_list[MAXDEG * BN];
__device__ int g_cnt[MAXDEG];
__device__ __nv_bfloat16 g_wh[MAXDEG * FF * FF];   // W^T hi: [d][n][k]
__device__ __nv_bfloat16 g_wl[MAXDEG * FF * FF];   // W^T lo

__device__ __forceinline__ uint32_t smem_u32(const void* p) {
    uint32_t a;
    asm("{ .reg .u64 t; cvta.to.shared.u64 t, %1; cvt.u32.u64 %0, t; }" : "=r"(a) : "l"(p));
    return a;
}
__device__ __forceinline__ void ldm_x4(uint32_t& r0, uint32_t& r1, uint32_t& r2, uint32_t& r3,
                                       uint32_t addr) {
    asm volatile("ldmatrix.sync.aligned.m8n8.x4.shared.b16 {%0,%1,%2,%3}, [%4];"
                 : "=r"(r0), "=r"(r1), "=r"(r2), "=r"(r3) : "r"(addr));
}
__device__ __forceinline__ void mma16816(float* c, const uint32_t* a, uint32_t b0, uint32_t b1) {
    asm volatile("mma.sync.aligned.m16n8k16.row.col.f32.bf16.bf16.f32 "
                 "{%0,%1,%2,%3}, {%4,%5,%6,%7}, {%8,%9}, {%0,%1,%2,%3};"
                 : "+f"(c[0]), "+f"(c[1]), "+f"(c[2]), "+f"(c[3])
                 : "r"(a[0]), "r"(a[1]), "r"(a[2]), "r"(a[3]), "r"(b0), "r"(b1));
}

// ===================== kernel 0: zero counters =====================
__global__ void k_zero() {
    if (threadIdx.x < MAXDEG) g_cnt[threadIdx.x] = 0;
}

// ===================== kernel 1: bucket nodes by degree ============
__global__ void k_bucket(const int* __restrict__ edges) {
    __shared__ int c[MAXDEG];
    __shared__ int base[MAXDEG];
    int t = threadIdx.x;                    // 512 threads
    if (t < MAXDEG) c[t] = 0;
    __syncthreads();
    int node = blockIdx.x * 512 + t;
    int deg = 0;
#pragma unroll
    for (int s = 0; s < DD; s++) deg += (edges[node * DD + s] >= 0);
    if (deg >= MAXDEG) deg = MAXDEG - 1;
    int pos = atomicAdd(&c[deg], 1);
    __syncthreads();
    if (t < MAXDEG) base[t] = atomicAdd(&g_cnt[t], c[t]);
    __syncthreads();
    g_list[deg * BN + base[deg] + pos] = node;
}

// ===================== kernel 2: split+transpose W =================
__global__ void k_wsplit(const float* __restrict__ W) {
    int i = blockIdx.x * blockDim.x + threadIdx.x;   // < 6*128*128
    int d = i >> 14, rem = i & 16383, k = rem >> 7, n = rem & 127;
    float v = W[i];                                  // W[d][k][n]
    __nv_bfloat16 hi = __float2bfloat16(v);
    float lo = v - __bfloat162float(hi);
    int o = (d << 14) + (n << 7) + k;                // W^T[d][n][k]
    g_wh[o] = hi;
    g_wl[o] = __float2bfloat16(lo);
}

// ===================== kernel 3: fused gather + HMMA GEMM ==========
// grid (BN/TM, MAXDEG), 256 threads = 8 warps; warp w owns rows w*16..w*16+15
__global__ __launch_bounds__(256, 1)
void k_mma(const float* __restrict__ atoms,
           const int* __restrict__ edges,
           const float* __restrict__ bias,
           float* __restrict__ out) {
    const int d = blockIdx.y;
    const int cnt = g_cnt[d];
    const int tileBase = blockIdx.x * TM;
    if (tileBase >= cnt) return;

    extern __shared__ char smc[];
    const uint32_t sb = smem_u32(smc);

    const int tid = threadIdx.x;
    const int wid = tid >> 5;
    const int lid = tid & 31;

    int*   snode = (int*)(smc + SM_NODE);
    float* sbias = (float*)(smc + SM_BIAS);

    if (tid < TM) {
        int gi = tileBase + tid;
        snode[tid] = g_list[d * BN + (gi < cnt ? gi : cnt - 1)];
        sbias[tid] = bias[d * FF + tid];
    }
    __syncthreads();

    // ---- load W^T hi/lo tiles into padded smem: row n, k contiguous
    {
        const __nv_bfloat16* wh = g_wh + (d << 14);
        const __nv_bfloat16* wl = g_wl + (d << 14);
        for (int i = tid; i < FF * 16; i += 256) {
            int row = i >> 4, col = (i & 15) * 8;
            uint32_t so = (uint32_t)(row * SSTR + col) * 2;
            *(float4*)(smc + SM_WH + so) = *(const float4*)(wh + row * FF + col);
            *(float4*)(smc + SM_WL + so) = *(const float4*)(wl + row * FF + col);
        }
    }

    // ---- fused gather + sum + bf16 hi/lo split into smem
    {
        const int rr  = tid >> 3;          // 32 rows per pass
        const int c0  = (tid & 7) * 16;    // 16 cols per thread
#pragma unroll
        for (int p = 0; p < 4; p++) {
            int r = p * 32 + rr;
            int node = snode[r];
            const float4* Ap = (const float4*)(atoms + (size_t)node * FF + c0);
            float4 a0 = Ap[0], a1 = Ap[1], a2 = Ap[2], a3 = Ap[3];
            int eb = node * DD;
            int nb = (node >> 9) << 9;     // batch base (N=512)
#pragma unroll
            for (int s = 0; s < DD; s++) {
                int e = edges[eb + s];
                if (e >= 0) {
                    e = (e < NN) ? e : 0;
                    const float4* Np = (const float4*)(atoms + (size_t)(nb + e) * FF + c0);
                    float4 v0 = Np[0], v1 = Np[1], v2 = Np[2], v3 = Np[3];
                    a0.x += v0.x; a0.y += v0.y; a0.z += v0.z; a0.w += v0.w;
                    a1.x += v1.x; a1.y += v1.y; a1.z += v1.z; a1.w += v1.w;
                    a2.x += v2.x; a2.y += v2.y; a2.z += v2.z; a2.w += v2.w;
                    a3.x += v3.x; a3.y += v3.y; a3.z += v3.z; a3.w += v3.w;
                }
            }
            float vals[16] = {a0.x, a0.y, a0.z, a0.w, a1.x, a1.y, a1.z, a1.w,
                              a2.x, a2.y, a2.z, a2.w, a3.x, a3.y, a3.z, a3.w};
            uint32_t rowb = (uint32_t)(r * SSTR + c0) * 2;
#pragma unroll
            for (int j = 0; j < 8; j++) {
                float v0 = vals[2 * j], v1 = vals[2 * j + 1];
                __nv_bfloat16 h0 = __float2bfloat16(v0);
                __nv_bfloat16 h1 = __float2bfloat16(v1);
                __nv_bfloat16 l0 = __float2bfloat16(v0 - __bfloat162float(h0));
                __nv_bfloat16 l1 = __float2bfloat16(v1 - __bfloat162float(h1));
                uint32_t hp = ((uint32_t)__bfloat16_as_ushort(h1) << 16) | __bfloat16_as_ushort(h0);
                uint32_t lp = ((uint32_t)__bfloat16_as_ushort(l1) << 16) | __bfloat16_as_ushort(l0);
                *(uint32_t*)(smc + SM_SH + rowb + 4 * j) = hp;
                *(uint32_t*)(smc + SM_SL + rowb + 4 * j) = lp;
            }
        }
    }
    __syncthreads();

    // ---- warp MMA: D = Sh*Wh^T + Sh*Wl^T + Sl*Wh^T, single accumulator
    float acc[16][4];
#pragma unroll
    for (int t = 0; t < 16; t++)
#pragma unroll
        for (int q = 0; q < 4; q++) acc[t][q] = 0.f;

    const int wrow = wid * 16;
    // A ldmatrix lane address (row/col-block per lane)
    const int arow = wrow + (lid & 7) + ((lid >> 3) & 1) * 8;
    const int acol = ((lid >> 4) & 1) * 8;
    const uint32_t aoff = (uint32_t)(arow * SSTR + acol) * 2;
    // B ldmatrix lane pattern
    const int bnl  = (lid & 7) + ((lid >> 4) & 1) * 8;
    const int bcol = ((lid >> 3) & 1) * 8;

#pragma unroll
    for (int kb = 0; kb < 8; kb++) {
        const uint32_t kbyte = (uint32_t)kb * 32;   // 16 bf16
        uint32_t ah[4], al[4];
        ldm_x4(ah[0], ah[1], ah[2], ah[3], sb + SM_SH + aoff + kbyte);
        ldm_x4(al[0], al[1], al[2], al[3], sb + SM_SL + aoff + kbyte);
#pragma unroll
        for (int p = 0; p < 8; p++) {
            uint32_t boff = (uint32_t)((p * 16 + bnl) * SSTR + bcol) * 2 + kbyte;
            uint32_t bh0, bh1, bh2, bh3, bl0, bl1, bl2, bl3;
            ldm_x4(bh0, bh1, bh2, bh3, sb + SM_WH + boff);
            ldm_x4(bl0, bl1, bl2, bl3, sb + SM_WL + boff);
            mma16816(acc[2 * p],     ah, bh0, bh1);
            mma16816(acc[2 * p],     ah, bl0, bl1);
            mma16816(acc[2 * p],     al, bh0, bh1);
            mma16816(acc[2 * p + 1], ah, bh2, bh3);
            mma16816(acc[2 * p + 1], ah, bl2, bl3);
            mma16816(acc[2 * p + 1], al, bh2, bh3);
        }
    }

    // ---- epilogue: bias + relu + scatter store (float2 per tile-row)
    {
        const int r0 = wrow + (lid >> 2);
        const int r1 = r0 + 8;
        const bool ok0 = (tileBase + r0) < cnt;
        const bool ok1 = (tileBase + r1) < cnt;
        float* op0 = out + (size_t)snode[r0] * FF;
        float* op1 = out + (size_t)snode[r1] * FF;
        const int cb = (lid & 3) * 2;
#pragma unroll
        for (int t = 0; t < 16; t++) {
            int c = t * 8 + cb;
            float b0 = sbias[c], b1 = sbias[c + 1];
            if (ok0) {
                float x0 = fmaxf(acc[t][0] + b0, 0.f);
                float x1 = fmaxf(acc[t][1] + b1, 0.f);
                *(float2*)(op0 + c) = make_float2(x0, x1);
            }
            if (ok1) {
                float x2 = fmaxf(acc[t][2] + b0, 0.f);
                float x3 = fmaxf(acc[t][3] + b1, 0.f);
                *(float2*)(op1 + c) = make_float2(x2, x3);
            }
        }
    }
}

// ===================== launch =====================
extern "C" void kernel_launch(void* const* d_in, const int* in_sizes, int n_in,
                              void* d_out, int out_size) {
    const float* atoms = (const float*)d_in[0];
    const int*   edges = (const int*)d_in[1];
    const float* W     = (const float*)d_in[2];
    const float* bias  = (const float*)d_in[3];
    float*       out   = (float*)d_out;

    cudaFuncSetAttribute(k_mma, cudaFuncAttributeMaxDynamicSharedMemorySize, SM_BYTES);

    k_zero<<<1, 32>>>();
    k_bucket<<<BN / 512, 512>>>(edges);
    k_wsplit<<<(MAXDEG * FF * FF) / 256, 256>>>(W);
    k_mma<<<dim3(BN / TM, MAXDEG), 256, SM_BYTES>>>(atoms, edges, bias, out);
}

// round 7
// speedup vs baseline: 1.4285x; 1.4285x over previous
#include <cuda_runtime.h>
#include <cuda_bf16.h>
#include <cstdint>

#define BB 256
#define NN 512
#define DD 6
#define FF 128
#define MAXDEG 6
#define BN (BB * NN)
#define TM 128
#define SSTR 136   // smem row stride in bf16 elems (128 + 8 pad)
#define NCH 64     // N chunk (output cols per phase)

// ---- smem byte offsets ----
#define SM_SH   0                       // Sh: 128 x SSTR bf16 = 34816B
#define SM_SL   34816                   // Sl
#define SM_WH   69632                   // Wh chunk: 64 x SSTR bf16 = 17408B
#define SM_WL   87040                   // Wl chunk
#define SM_NODE 104448                  // 128 ints
#define SM_BIAS 104960                  // 128 floats
#define SM_BYTES 105472

// ---- device scratch (allocation-free rule) ----
__device__ int g_list[MAXDEG * BN];
__device__ int g_cnt[MAXDEG];
__device__ __nv_bfloat16 g_wh[MAXDEG * FF * FF];   // W^T hi: [d][n][k]
__device__ __nv_bfloat16 g_wl[MAXDEG * FF * FF];   // W^T lo

__device__ __forceinline__ uint32_t smem_u32(const void* p) {
    uint32_t a;
    asm("{ .reg .u64 t; cvta.to.shared.u64 t, %1; cvt.u32.u64 %0, t; }" : "=r"(a) : "l"(p));
    return a;
}
__device__ __forceinline__ void ldm_x4(uint32_t& r0, uint32_t& r1, uint32_t& r2, uint32_t& r3,
                                       uint32_t addr) {
    asm volatile("ldmatrix.sync.aligned.m8n8.x4.shared.b16 {%0,%1,%2,%3}, [%4];"
                 : "=r"(r0), "=r"(r1), "=r"(r2), "=r"(r3) : "r"(addr));
}
__device__ __forceinline__ void mma16816(float* c, const uint32_t* a, uint32_t b0, uint32_t b1) {
    asm volatile("mma.sync.aligned.m16n8k16.row.col.f32.bf16.bf16.f32 "
                 "{%0,%1,%2,%3}, {%4,%5,%6,%7}, {%8,%9}, {%0,%1,%2,%3};"
                 : "+f"(c[0]), "+f"(c[1]), "+f"(c[2]), "+f"(c[3])
                 : "r"(a[0]), "r"(a[1]), "r"(a[2]), "r"(a[3]), "r"(b0), "r"(b1));
}

// ===================== kernel 0: zero counters =====================
__global__ void k_zero() {
    if (threadIdx.x < MAXDEG) g_cnt[threadIdx.x] = 0;
}

// ===================== kernel 1: bucket nodes by degree ============
__global__ void k_bucket(const int* __restrict__ edges) {
    __shared__ int c[MAXDEG];
    __shared__ int base[MAXDEG];
    int t = threadIdx.x;                    // 512 threads
    if (t < MAXDEG) c[t] = 0;
    __syncthreads();
    int node = blockIdx.x * 512 + t;
    int deg = 0;
#pragma unroll
    for (int s = 0; s < DD; s++) deg += (edges[node * DD + s] >= 0);
    if (deg >= MAXDEG) deg = MAXDEG - 1;
    int pos = atomicAdd(&c[deg], 1);
    __syncthreads();
    if (t < MAXDEG) base[t] = atomicAdd(&g_cnt[t], c[t]);
    __syncthreads();
    g_list[deg * BN + base[deg] + pos] = node;
}

// ===================== kernel 2: split+transpose W =================
__global__ void k_wsplit(const float* __restrict__ W) {
    int i = blockIdx.x * blockDim.x + threadIdx.x;   // < 6*128*128
    int d = i >> 14, rem = i & 16383, k = rem >> 7, n = rem & 127;
    float v = W[i];                                  // W[d][k][n]
    __nv_bfloat16 hi = __float2bfloat16(v);
    float lo = v - __bfloat162float(hi);
    int o = (d << 14) + (n << 7) + k;                // W^T[d][n][k]
    g_wh[o] = hi;
    g_wl[o] = __float2bfloat16(lo);
}

// ===================== kernel 3: fused gather + HMMA GEMM ==========
// grid (BN/TM, MAXDEG), 256 threads = 8 warps; warp w owns rows w*16..w*16+15
// Two N-phases of 64 output cols each (W chunk staged per phase).
__global__ __launch_bounds__(256, 2)
void k_mma(const float* __restrict__ atoms,
           const int* __restrict__ edges,
           const float* __restrict__ bias,
           float* __restrict__ out) {
    const int d = blockIdx.y;
    const int cnt = g_cnt[d];
    const int tileBase = blockIdx.x * TM;
    if (tileBase >= cnt) return;

    extern __shared__ char smc[];
    const uint32_t sb = smem_u32(smc);

    const int tid = threadIdx.x;
    const int wid = tid >> 5;
    const int lid = tid & 31;

    int*   snode = (int*)(smc + SM_NODE);
    float* sbias = (float*)(smc + SM_BIAS);

    if (tid < TM) {
        int gi = tileBase + tid;
        snode[tid] = g_list[d * BN + (gi < cnt ? gi : cnt - 1)];
        sbias[tid] = bias[d * FF + tid];
    }
    __syncthreads();

    // ---- stage W chunk for phase 0 (issue LDGs early, they overlap gather)
    const __nv_bfloat16* wh = g_wh + (d << 14);
    const __nv_bfloat16* wl = g_wl + (d << 14);
    for (int i = tid; i < NCH * 16; i += 256) {       // 64 rows x 16 8-elem chunks
        int row = i >> 4, col = (i & 15) * 8;
        uint32_t so = (uint32_t)(row * SSTR + col) * 2;
        *(float4*)(smc + SM_WH + so) = *(const float4*)(wh + row * FF + col);
        *(float4*)(smc + SM_WL + so) = *(const float4*)(wl + row * FF + col);
    }

    // ---- fused gather + sum + bf16 hi/lo split into smem
    {
        const int rr  = tid >> 3;          // 32 rows per pass
        const int c0  = (tid & 7) * 16;    // 16 cols per thread
#pragma unroll
        for (int p = 0; p < 4; p++) {
            int r = p * 32 + rr;
            int node = snode[r];
            const float4* Ap = (const float4*)(atoms + (size_t)node * FF + c0);
            float4 a0 = Ap[0], a1 = Ap[1], a2 = Ap[2], a3 = Ap[3];
            int eb = node * DD;
            int nb = (node >> 9) << 9;     // batch base (N=512)
#pragma unroll
            for (int s = 0; s < DD; s++) {
                int e = edges[eb + s];
                if (e >= 0) {
                    e = (e < NN) ? e : 0;
                    const float4* Np = (const float4*)(atoms + (size_t)(nb + e) * FF + c0);
                    float4 v0 = Np[0], v1 = Np[1], v2 = Np[2], v3 = Np[3];
                    a0.x += v0.x; a0.y += v0.y; a0.z += v0.z; a0.w += v0.w;
                    a1.x += v1.x; a1.y += v1.y; a1.z += v1.z; a1.w += v1.w;
                    a2.x += v2.x; a2.y += v2.y; a2.z += v2.z; a2.w += v2.w;
                    a3.x += v3.x; a3.y += v3.y; a3.z += v3.z; a3.w += v3.w;
                }
            }
            float vals[16] = {a0.x, a0.y, a0.z, a0.w, a1.x, a1.y, a1.z, a1.w,
                              a2.x, a2.y, a2.z, a2.w, a3.x, a3.y, a3.z, a3.w};
            uint32_t rowb = (uint32_t)(r * SSTR + c0) * 2;
#pragma unroll
            for (int j = 0; j < 8; j++) {
                float v0 = vals[2 * j], v1 = vals[2 * j + 1];
                __nv_bfloat16 h0 = __float2bfloat16(v0);
                __nv_bfloat16 h1 = __float2bfloat16(v1);
                __nv_bfloat16 l0 = __float2bfloat16(v0 - __bfloat162float(h0));
                __nv_bfloat16 l1 = __float2bfloat16(v1 - __bfloat162float(h1));
                uint32_t hp = ((uint32_t)__bfloat16_as_ushort(h1) << 16) | __bfloat16_as_ushort(h0);
                uint32_t lp = ((uint32_t)__bfloat16_as_ushort(l1) << 16) | __bfloat16_as_ushort(l0);
                *(uint32_t*)(smc + SM_SH + rowb + 4 * j) = hp;
                *(uint32_t*)(smc + SM_SL + rowb + 4 * j) = lp;
            }
        }
    }
    __syncthreads();

    // ---- lane-invariant fragment addressing ----
    const int wrow = wid * 16;
    const int arow = wrow + (lid & 7) + ((lid >> 3) & 1) * 8;
    const int acol = ((lid >> 4) & 1) * 8;
    const uint32_t aoff = (uint32_t)(arow * SSTR + acol) * 2;
    const int bnl  = (lid & 7) + ((lid >> 4) & 1) * 8;
    const int bcol = ((lid >> 3) & 1) * 8;

    const int r0 = wrow + (lid >> 2);
    const int r1 = r0 + 8;
    const bool ok0 = (tileBase + r0) < cnt;
    const bool ok1 = (tileBase + r1) < cnt;
    float* op0 = out + (size_t)snode[r0] * FF;
    float* op1 = out + (size_t)snode[r1] * FF;
    const int cb = (lid & 3) * 2;

#pragma unroll
    for (int ph = 0; ph < 2; ph++) {
        if (ph == 1) {
            __syncthreads();               // all warps done reading W chunk 0
            for (int i = tid; i < NCH * 16; i += 256) {
                int row = i >> 4, col = (i & 15) * 8;
                uint32_t so = (uint32_t)(row * SSTR + col) * 2;
                *(float4*)(smc + SM_WH + so) = *(const float4*)(wh + (NCH + row) * FF + col);
                *(float4*)(smc + SM_WL + so) = *(const float4*)(wl + (NCH + row) * FF + col);
            }
            __syncthreads();
        }

        float acc[8][4];
#pragma unroll
        for (int t = 0; t < 8; t++)
#pragma unroll
            for (int q = 0; q < 4; q++) acc[t][q] = 0.f;

#pragma unroll
        for (int kb = 0; kb < 8; kb++) {
            const uint32_t kbyte = (uint32_t)kb * 32;   // 16 bf16
            uint32_t ah[4], al[4];
            ldm_x4(ah[0], ah[1], ah[2], ah[3], sb + SM_SH + aoff + kbyte);
            ldm_x4(al[0], al[1], al[2], al[3], sb + SM_SL + aoff + kbyte);
            uint32_t bh[4][4], bl[4][4];
#pragma unroll
            for (int p = 0; p < 4; p++) {
                uint32_t boff = (uint32_t)((p * 16 + bnl) * SSTR + bcol) * 2 + kbyte;
                ldm_x4(bh[p][0], bh[p][1], bh[p][2], bh[p][3], sb + SM_WH + boff);
                ldm_x4(bl[p][0], bl[p][1], bl[p][2], bl[p][3], sb + SM_WL + boff);
            }
            // term-major order: consecutive MMAs hit different accumulators
#pragma unroll
            for (int p = 0; p < 4; p++) {
                mma16816(acc[2 * p],     ah, bh[p][0], bh[p][1]);
                mma16816(acc[2 * p + 1], ah, bh[p][2], bh[p][3]);
            }
#pragma unroll
            for (int p = 0; p < 4; p++) {
                mma16816(acc[2 * p],     ah, bl[p][0], bl[p][1]);
                mma16816(acc[2 * p + 1], ah, bl[p][2], bl[p][3]);
            }
#pragma unroll
            for (int p = 0; p < 4; p++) {
                mma16816(acc[2 * p],     al, bh[p][0], bh[p][1]);
                mma16816(acc[2 * p + 1], al, bh[p][2], bh[p][3]);
            }
        }

        // ---- epilogue for this 64-col phase
        const int cbase = ph * NCH;
#pragma unroll
        for (int t = 0; t < 8; t++) {
            int c = cbase + t * 8 + cb;
            float b0 = sbias[c], b1 = sbias[c + 1];
            if (ok0) {
                float x0 = fmaxf(acc[t][0] + b0, 0.f);
                float x1 = fmaxf(acc[t][1] + b1, 0.f);
                *(float2*)(op0 + c) = make_float2(x0, x1);
            }
            if (ok1) {
                float x2 = fmaxf(acc[t][2] + b0, 0.f);
                float x3 = fmaxf(acc[t][3] + b1, 0.f);
                *(float2*)(op1 + c) = make_float2(x2, x3);
            }
        }
    }
}

// ===================== launch =====================
extern "C" void kernel_launch(void* const* d_in, const int* in_sizes, int n_in,
                              void* d_out, int out_size) {
    const float* atoms = (const float*)d_in[0];
    const int*   edges = (const int*)d_in[1];
    const float* W     = (const float*)d_in[2];
    const float* bias  = (const float*)d_in[3];
    float*       out   = (float*)d_out;

    cudaFuncSetAttribute(k_mma, cudaFuncAttributeMaxDynamicSharedMemorySize, SM_BYTES);

    k_zero<<<1, 32>>>();
    k_bucket<<<BN / 512, 512>>>(edges);
    k_wsplit<<<(MAXDEG * FF * FF) / 256, 256>>>(W);
    k_mma<<<dim3(BN / TM, MAXDEG), 256, SM_BYTES>>>(atoms, edges, bias, out);
}